// round 13
// baseline (speedup 1.0000x reference)
#include <cuda_runtime.h>
#include <cuda_fp16.h>

typedef unsigned int u32;

// Problem constants
#define S_LEN 8192
#define BATCH 8
#define DM    128
#define NQKV  384
#define MT1   64             // rows per k1 block
#define NKC   16             // split-K chunks (kernel 2)
#define KCH   (S_LEN/NKC)    // 512

// ---- scratch (device globals; no cudaMalloc anywhere) ----
__device__ __align__(16) __half g_attn_h[BATCH * S_LEN * DM];   // 16.7 MB attn out (fp16)
__device__ float g_part[NKC * BATCH * DM * DM];                 // 8 MB split-K partials
__device__ __align__(16) __half g_wq[DM * NQKV];                // W_qkv fp16 [k][n]
__device__ int g_cnt[BATCH * 2];                                // per-(b,mb) completion counters

// ---- k1 smem layout (bytes) ----
#define SM_BIAS 0                         // 384 f32 = 1536
#define SM_A    1536                      // [64][136] fp16 = 17408
#define SM_B    (SM_A + 17408)            // [128][136] fp16 = 34816
#define SM_ST   (SM_B + 34816)            // [64][404] fp16 = 51712
#define SM_TOT  (SM_ST + 51712)           // 105472 B -> 2 CTA/SM
#define STP     404                       // pitch in halves: 808 B rows (8B-aligned, 8B-stride 101 -> conflict-free)

// ---------------------------------------------------------------------------
__device__ __forceinline__ u32 smem_u32(const void* p) {
    u32 a;
    asm("{ .reg .u64 t; cvta.to.shared.u64 t, %1; cvt.u32.u64 %0, t; }" : "=r"(a) : "l"(p));
    return a;
}
__device__ __forceinline__ void ldsm4(u32* r, u32 a) {
    asm volatile("ldmatrix.sync.aligned.m8n8.x4.shared.b16 {%0,%1,%2,%3}, [%4];"
        : "=r"(r[0]), "=r"(r[1]), "=r"(r[2]), "=r"(r[3]) : "r"(a));
}
__device__ __forceinline__ void ldsm4t(u32* r, u32 a) {
    asm volatile("ldmatrix.sync.aligned.m8n8.x4.trans.shared.b16 {%0,%1,%2,%3}, [%4];"
        : "=r"(r[0]), "=r"(r[1]), "=r"(r[2]), "=r"(r[3]) : "r"(a));
}
__device__ __forceinline__ void mma16816(float* d, const u32* a, const u32* b) {
    asm volatile(
        "mma.sync.aligned.m16n8k16.row.col.f32.f16.f16.f32 "
        "{%0,%1,%2,%3}, {%4,%5,%6,%7}, {%8,%9}, {%0,%1,%2,%3};"
        : "+f"(d[0]), "+f"(d[1]), "+f"(d[2]), "+f"(d[3])
        : "r"(a[0]), "r"(a[1]), "r"(a[2]), "r"(a[3]), "r"(b[0]), "r"(b[1]));
}
__device__ __forceinline__ uint2 cvt_h4(float4 v) {
    __half2 a = __floats2half2_rn(v.x, v.y);
    __half2 b = __floats2half2_rn(v.z, v.w);
    uint2 r;
    r.x = *(u32*)&a;
    r.y = *(u32*)&b;
    return r;
}
__device__ __forceinline__ u32 cvt_h2(float a, float b) {
    __half2 h = __floats2half2_rn(a, b);
    return *(u32*)&h;
}
// load 4 halves at p (8B aligned) -> 4 floats
__device__ __forceinline__ void ld_h4f(const __half* p, float* f) {
    uint2 v = *(const uint2*)p;
    float2 a = __half22float2(*(__half2*)&v.x);
    float2 b = __half22float2(*(__half2*)&v.y);
    f[0] = a.x; f[1] = a.y; f[2] = b.x; f[3] = b.y;
}

// ---------------------------------------------------------------------------
// k0a: one-time W_qkv fp32 -> fp16
// ---------------------------------------------------------------------------
__global__ void k0a_convWq(const float* __restrict__ W)
{
    int idx = blockIdx.x * 256 + threadIdx.x;
    if (idx < DM * NQKV) g_wq[idx] = __float2half_rn(W[idx]);
}

// ---------------------------------------------------------------------------
// k1: qkv = x @ W_qkv + b via fp16 mma.sync; per-position HxH attention
//     (4 threads/position, constant indexing only); fp16 attn out
// ---------------------------------------------------------------------------
__global__ __launch_bounds__(256, 2)
void k1_qkv_attn(const float* __restrict__ x, const float* __restrict__ bqkv)
{
    extern __shared__ char smem[];
    const u32 sb  = smem_u32(smem);
    const int tid = threadIdx.x;
    const int lane = tid & 31, wid = tid >> 5;
    const int mbase = blockIdx.x * MT1;

    float* sbias = (float*)(smem + SM_BIAS);
    for (int i = tid; i < NQKV; i += 256) sbias[i] = bqkv[i];

    // A tile: 64x128 fp32 -> fp16, pitch 136
    {
        const float4* xg = (const float4*)(x + (size_t)mbase * DM);
        #pragma unroll
        for (int t = 0; t < 8; t++) {
            int f = tid + 256 * t;              // 2048 float4
            int row = f >> 5, k0 = (f & 31) * 4;
            *(uint2*)(smem + SM_A + (row * 136 + k0) * 2) = cvt_h4(xg[f]);
        }
    }
    // B tile nt=0
    {
        const uint4* src = (const uint4*)g_wq;   // rows of 48 uint4 (384 fp16)
        #pragma unroll
        for (int t = 0; t < 8; t++) {
            int f = tid + 256 * t;               // 2048 uint4
            int row = f >> 4, c8 = (f & 15);
            *(uint4*)(smem + SM_B + (row * 136 + c8 * 8) * 2) = src[row * 48 + c8];
        }
    }
    __syncthreads();

    const int m0 = (wid >> 2) * 32;     // 2 M-groups of 32 rows
    const int n0 = (wid & 3) * 32;      // 4 N-groups of 32 cols
    const u32 arow = (u32)(lane & 15);
    const u32 csel = (u32)((lane >> 4) << 3);
    __half* St = (__half*)(smem + SM_ST);

    for (int nt = 0; nt < 3; nt++) {
        float acc[2][4][4];
        #pragma unroll
        for (int mf = 0; mf < 2; mf++)
            #pragma unroll
            for (int nf = 0; nf < 4; nf++)
                #pragma unroll
                for (int r = 0; r < 4; r++) acc[mf][nf][r] = 0.f;

        #pragma unroll
        for (int ks = 0; ks < 8; ks++) {
            const int k0 = ks * 16;
            u32 a[2][4], bfr[4][2];
            #pragma unroll
            for (int mf = 0; mf < 2; mf++)
                ldsm4(a[mf], sb + SM_A + ((m0 + mf * 16 + arow) * 136 + csel + k0) * 2);
            #pragma unroll
            for (int h2 = 0; h2 < 2; h2++) {
                u32 r[4];
                ldsm4t(r, sb + SM_B + ((k0 + arow) * 136 + n0 + h2 * 16 + csel) * 2);
                bfr[h2*2][0] = r[0];   bfr[h2*2][1] = r[1];
                bfr[h2*2+1][0] = r[2]; bfr[h2*2+1][1] = r[3];
            }
            #pragma unroll
            for (int mf = 0; mf < 2; mf++)
                #pragma unroll
                for (int nf = 0; nf < 4; nf++)
                    mma16816(acc[mf][nf], a[mf], bfr[nf]);
        }

        // stage accum (+bias) to St as fp16 pairs
        {
            const int r0 = m0 + (lane >> 2);
            const int cb = nt * 128 + n0 + (lane & 3) * 2;
            #pragma unroll
            for (int mf = 0; mf < 2; mf++)
                #pragma unroll
                for (int nf = 0; nf < 4; nf++) {
                    int row = r0 + mf * 16, col = cb + nf * 8;
                    float b0 = sbias[col], b1 = sbias[col + 1];
                    *(u32*)&St[row * STP + col] =
                        cvt_h2(acc[mf][nf][0] + b0, acc[mf][nf][1] + b1);
                    *(u32*)&St[(row + 8) * STP + col] =
                        cvt_h2(acc[mf][nf][2] + b0, acc[mf][nf][3] + b1);
                }
        }

        if (nt < 2) {
            __syncthreads();    // all warps done reading current B tile
            const uint4* src = (const uint4*)g_wq;
            const int gc8 = (nt + 1) * 16;
            #pragma unroll
            for (int t = 0; t < 8; t++) {
                int f = tid + 256 * t;
                int row = f >> 4, c8 = (f & 15);
                *(uint4*)(smem + SM_B + (row * 136 + c8 * 8) * 2) = src[row * 48 + gc8 + c8];
            }
            __syncthreads();
        }
    }
    __syncthreads();

    // Attention: 4 threads per position (pos = tid>>2, h1 = tid&3).
    {
        const int pos = tid >> 2, h1 = tid & 3;
        const __half* rp = St + pos * STP;   // [h*96 + {q:0..31, k:32..63, v:64..95}]

        float s[4] = {0.f, 0.f, 0.f, 0.f};
        #pragma unroll
        for (int d4 = 0; d4 < 8; d4++) {
            float q4[4];
            ld_h4f(rp + h1 * 96 + d4 * 4, q4);
            #pragma unroll
            for (int h2 = 0; h2 < 4; h2++) {
                float k4[4];
                ld_h4f(rp + h2 * 96 + 32 + d4 * 4, k4);
                #pragma unroll
                for (int e = 0; e < 4; e++) s[h2] = fmaf(q4[e], k4[e], s[h2]);
            }
        }

        const float scale = 0.17677669529663687f;  // 32^-0.5
        float t0 = s[0]*scale, t1 = s[1]*scale, t2 = s[2]*scale, t3 = s[3]*scale;
        float m  = fmaxf(fmaxf(t0, t1), fmaxf(t2, t3));
        float e0 = __expf(t0 - m), e1 = __expf(t1 - m);
        float e2 = __expf(t2 - m), e3 = __expf(t3 - m);
        float inv = 1.f / (e0 + e1 + e2 + e3);
        float w0 = e0*inv, w1 = e1*inv, w2 = e2*inv, w3 = e3*inv;

        u32 hw[16];
        #pragma unroll
        for (int d4 = 0; d4 < 8; d4++) {
            float o[4] = {0.f, 0.f, 0.f, 0.f};
            float v4[4];
            ld_h4f(rp + 0*96 + 64 + d4*4, v4);
            #pragma unroll
            for (int e = 0; e < 4; e++) o[e] = fmaf(w0, v4[e], o[e]);
            ld_h4f(rp + 1*96 + 64 + d4*4, v4);
            #pragma unroll
            for (int e = 0; e < 4; e++) o[e] = fmaf(w1, v4[e], o[e]);
            ld_h4f(rp + 2*96 + 64 + d4*4, v4);
            #pragma unroll
            for (int e = 0; e < 4; e++) o[e] = fmaf(w2, v4[e], o[e]);
            ld_h4f(rp + 3*96 + 64 + d4*4, v4);
            #pragma unroll
            for (int e = 0; e < 4; e++) o[e] = fmaf(w3, v4[e], o[e]);
            hw[d4*2]     = cvt_h2(o[0], o[1]);
            hw[d4*2 + 1] = cvt_h2(o[2], o[3]);
        }

        __half* outp = g_attn_h + (size_t)(mbase + pos) * DM + h1 * 32;
        #pragma unroll
        for (int t = 0; t < 4; t++) {
            uint4 v = make_uint4(hw[4*t], hw[4*t+1], hw[4*t+2], hw[4*t+3]);
            *(uint4*)(outp + t * 8) = v;
        }
    }
}

// ---------------------------------------------------------------------------
// k2: split-K+M partials + fused last-block reduction (threadFenceReduction)
//   grid (NKC, 2, BATCH); each block: 64 rows x 128 cols, K=512
//   Last-arriving block per (b,mb) region reduces 16 partials + bias -> out.
//   Deterministic: reduction done by ONE block in fixed ascending-kc order.
// ---------------------------------------------------------------------------
__global__ __launch_bounds__(256, 1)
void k2_partial(const float* __restrict__ Wout, const float* __restrict__ bout,
                float* __restrict__ out)
{
    __shared__ __align__(16) __half As2[2][64 * 40];    // pitch 40
    __shared__ __align__(16) __half Bs2[2][32 * 136];   // pitch 136
    __shared__ int s_last;
    const u32 sa = smem_u32(As2);
    const u32 sbm = smem_u32(Bs2);

    const int tid = threadIdx.x;
    const int lane = tid & 31, wid = tid >> 5;
    const int kc = blockIdx.x, mb = blockIdx.y, b = blockIdx.z;
    const __half* Ab = g_attn_h + (size_t)b * DM * S_LEN + (size_t)mb * 64 * S_LEN;
    const int kb0 = kc * KCH;

    const int m0 = (wid >> 2) * 32;     // 2 warp-rows of 32
    const int n0 = (wid & 3) * 32;
    const u32 arow = (u32)(lane & 15);
    const u32 csel = (u32)((lane >> 4) << 3);

    float acc[2][4][4];
    #pragma unroll
    for (int mf = 0; mf < 2; mf++)
        #pragma unroll
        for (int nf = 0; nf < 4; nf++)
            #pragma unroll
            for (int r = 0; r < 4; r++) acc[mf][nf][r] = 0.f;

    uint4 pa;
    float4 pbf[4];
    auto gload = [&](int c) {
        const int kpos = kb0 + c * 32;
        pa = *(const uint4*)&Ab[(size_t)(tid >> 2) * S_LEN + kpos + (tid & 3) * 8];
        #pragma unroll
        for (int t = 0; t < 4; t++) {
            int f = tid + 256 * t;
            int kk = f >> 5, n4 = (f & 31) * 4;
            pbf[t] = *(const float4*)&Wout[(size_t)(kpos + kk) * DM + n4];
        }
    };
    auto sstore = [&](int buf) {
        *(uint4*)&As2[buf][(tid >> 2) * 40 + (tid & 3) * 8] = pa;
        #pragma unroll
        for (int t = 0; t < 4; t++) {
            int f = tid + 256 * t;
            int kk = f >> 5, n4 = (f & 31) * 4;
            *(uint2*)&Bs2[buf][kk * 136 + n4] = cvt_h4(pbf[t]);
        }
    };

    gload(0); sstore(0); __syncthreads();

    int buf = 0;
    for (int c = 0; c < 16; c++) {
        if (c < 15) gload(c + 1);
        #pragma unroll
        for (int kk = 0; kk < 32; kk += 16) {
            u32 a[2][4], bfr[4][2];
            #pragma unroll
            for (int h2 = 0; h2 < 2; h2++) {
                u32 r[4];
                ldsm4t(r, sbm + (u32)buf * (32*136*2) +
                          ((kk + arow) * 136 + n0 + h2 * 16 + csel) * 2);
                bfr[h2*2][0] = r[0];   bfr[h2*2][1] = r[1];
                bfr[h2*2+1][0] = r[2]; bfr[h2*2+1][1] = r[3];
            }
            #pragma unroll
            for (int mf = 0; mf < 2; mf++)
                ldsm4(a[mf], sa + (u32)buf * (64*40*2) +
                             ((m0 + mf * 16 + arow) * 40 + csel + kk) * 2);
            #pragma unroll
            for (int mf = 0; mf < 2; mf++)
                #pragma unroll
                for (int nf = 0; nf < 4; nf++)
                    mma16816(acc[mf][nf], a[mf], bfr[nf]);
        }
        if (c < 15) sstore(buf ^ 1);
        __syncthreads();
        buf ^= 1;
    }

    // store partial
    float* pp = g_part + (size_t)(b * NKC + kc) * DM * DM;
    const int r0 = mb * 64 + m0 + (lane >> 2);
    const int cb = n0 + (lane & 3) * 2;
    #pragma unroll
    for (int mf = 0; mf < 2; mf++)
        #pragma unroll
        for (int nf = 0; nf < 4; nf++) {
            int row = r0 + mf * 16, col = cb + nf * 8;
            *(float2*)&pp[row * DM + col] = make_float2(acc[mf][nf][0], acc[mf][nf][1]);
            *(float2*)&pp[(row + 8) * DM + col] = make_float2(acc[mf][nf][2], acc[mf][nf][3]);
        }

    // last-block reduction for this (b, mb) region
    __threadfence();
    __syncthreads();
    if (tid == 0) {
        const int ci = b * 2 + mb;
        int old = atomicAdd(&g_cnt[ci], 1);
        s_last = (old == NKC - 1);
        if (s_last) g_cnt[ci] = 0;    // self-reset for graph replays
    }
    __syncthreads();
    if (s_last) {
        const float* base = g_part + (size_t)b * NKC * DM * DM + (size_t)(mb * 64) * DM;
        float* op = out + (size_t)b * DM * DM + (size_t)(mb * 64) * DM;
        #pragma unroll
        for (int it = 0; it < 16; it++) {
            int f = tid + 256 * it;          // 0..4095 float2 over 64x64
            int row = f >> 6, c2 = f & 63;
            float2 s = *(const float2*)&bout[c2 * 2];
            const float* p = base + row * DM + c2 * 2;
            #pragma unroll
            for (int kc2 = 0; kc2 < NKC; kc2++) {
                float2 v = *(const float2*)&p[(size_t)kc2 * DM * DM];
                s.x += v.x; s.y += v.y;
            }
            *(float2*)&op[row * DM + c2 * 2] = s;
        }
    }
}

// ---------------------------------------------------------------------------
extern "C" void kernel_launch(void* const* d_in, const int* in_sizes, int n_in,
                              void* d_out, int out_size)
{
    const float* x    = (const float*)d_in[0];
    const float* Wqkv = (const float*)d_in[1];
    const float* bqkv = (const float*)d_in[2];
    const float* Wout = (const float*)d_in[3];
    const float* bout = (const float*)d_in[4];
    float* out = (float*)d_out;

    cudaFuncSetAttribute(k1_qkv_attn,
                         cudaFuncAttributeMaxDynamicSharedMemorySize, SM_TOT);

    k0a_convWq<<<(DM * NQKV + 255) / 256, 256>>>(Wqkv);

    k1_qkv_attn<<<(BATCH * S_LEN) / MT1, 256, SM_TOT>>>(x, bqkv);

    dim3 g2(NKC, 2, BATCH);
    k2_partial<<<g2, 256>>>(Wout, bout, out);
}

// round 14
// speedup vs baseline: 1.1023x; 1.1023x over previous
#include <cuda_runtime.h>
#include <cuda_fp16.h>

typedef unsigned int u32;

// Problem constants
#define S_LEN 8192
#define BATCH 8
#define DM    128
#define NQKV  384
#define MT1   64             // rows per k1 block
#define NKC   16             // split-K chunks (kernel 2)
#define KCH   (S_LEN/NKC)    // 512

// ---- scratch (device globals; no cudaMalloc anywhere) ----
__device__ __align__(16) __half g_attn_h[BATCH * S_LEN * DM];   // 16.7 MB attn out (fp16)
__device__ float g_part[NKC * BATCH * DM * DM];                 // 8 MB split-K partials

// ---- k1 smem layout (bytes) ----
#define SM_BIAS 0                         // 384 f32 = 1536
#define SM_A    1536                      // [64][136] fp16 = 17408
#define SM_B    (SM_A + 17408)            // [128][136] fp16 = 34816
#define SM_ST   (SM_B + 34816)            // [64][404] fp16 = 51712
#define SM_TOT  (SM_ST + 51712)           // 105472 B -> 2 CTA/SM
#define STP     404                       // pitch in halves: 808 B rows (8B-aligned, 8B-stride 101 -> conflict-free)

// ---------------------------------------------------------------------------
__device__ __forceinline__ u32 smem_u32(const void* p) {
    u32 a;
    asm("{ .reg .u64 t; cvta.to.shared.u64 t, %1; cvt.u32.u64 %0, t; }" : "=r"(a) : "l"(p));
    return a;
}
__device__ __forceinline__ void ldsm4(u32* r, u32 a) {
    asm volatile("ldmatrix.sync.aligned.m8n8.x4.shared.b16 {%0,%1,%2,%3}, [%4];"
        : "=r"(r[0]), "=r"(r[1]), "=r"(r[2]), "=r"(r[3]) : "r"(a));
}
__device__ __forceinline__ void ldsm4t(u32* r, u32 a) {
    asm volatile("ldmatrix.sync.aligned.m8n8.x4.trans.shared.b16 {%0,%1,%2,%3}, [%4];"
        : "=r"(r[0]), "=r"(r[1]), "=r"(r[2]), "=r"(r[3]) : "r"(a));
}
__device__ __forceinline__ void mma16816(float* d, const u32* a, const u32* b) {
    asm volatile(
        "mma.sync.aligned.m16n8k16.row.col.f32.f16.f16.f32 "
        "{%0,%1,%2,%3}, {%4,%5,%6,%7}, {%8,%9}, {%0,%1,%2,%3};"
        : "+f"(d[0]), "+f"(d[1]), "+f"(d[2]), "+f"(d[3])
        : "r"(a[0]), "r"(a[1]), "r"(a[2]), "r"(a[3]), "r"(b[0]), "r"(b[1]));
}
__device__ __forceinline__ uint2 cvt_h4(float4 v) {
    __half2 a = __floats2half2_rn(v.x, v.y);
    __half2 b = __floats2half2_rn(v.z, v.w);
    uint2 r;
    r.x = *(u32*)&a;
    r.y = *(u32*)&b;
    return r;
}
__device__ __forceinline__ u32 cvt_h2(float a, float b) {
    __half2 h = __floats2half2_rn(a, b);
    return *(u32*)&h;
}
// load 4 halves at p (8B aligned) -> 4 floats
__device__ __forceinline__ void ld_h4f(const __half* p, float* f) {
    uint2 v = *(const uint2*)p;
    float2 a = __half22float2(*(__half2*)&v.x);
    float2 b = __half22float2(*(__half2*)&v.y);
    f[0] = a.x; f[1] = a.y; f[2] = b.x; f[3] = b.y;
}

// ---------------------------------------------------------------------------
// k1: qkv = x @ W_qkv + b via fp16 mma.sync; per-position HxH attention
//     (4 threads/position); W_qkv read fp32 + converted inline (no k0 kernel)
// ---------------------------------------------------------------------------
__global__ __launch_bounds__(256, 2)
void k1_qkv_attn(const float* __restrict__ x, const float* __restrict__ Wqkv,
                 const float* __restrict__ bqkv)
{
    extern __shared__ char smem[];
    const u32 sb  = smem_u32(smem);
    const int tid = threadIdx.x;
    const int lane = tid & 31, wid = tid >> 5;
    const int mbase = blockIdx.x * MT1;

    float* sbias = (float*)(smem + SM_BIAS);
    for (int i = tid; i < NQKV; i += 256) sbias[i] = bqkv[i];

    // A tile: 64x128 fp32 -> fp16, pitch 136
    {
        const float4* xg = (const float4*)(x + (size_t)mbase * DM);
        #pragma unroll
        for (int t = 0; t < 8; t++) {
            int f = tid + 256 * t;              // 2048 float4
            int row = f >> 5, k0 = (f & 31) * 4;
            *(uint2*)(smem + SM_A + (row * 136 + k0) * 2) = cvt_h4(xg[f]);
        }
    }
    // B tile nt=0: read W_qkv fp32 (L2-resident), convert inline
    {
        #pragma unroll
        for (int t = 0; t < 16; t++) {
            int f = tid + 256 * t;               // 4096 float4 (128 rows x 32)
            int row = f >> 5, c4 = (f & 31) * 4;
            float4 v = *(const float4*)&Wqkv[row * NQKV + c4];
            *(uint2*)(smem + SM_B + (row * 136 + c4) * 2) = cvt_h4(v);
        }
    }
    __syncthreads();

    const int m0 = (wid >> 2) * 32;     // 2 M-groups of 32 rows
    const int n0 = (wid & 3) * 32;      // 4 N-groups of 32 cols
    const u32 arow = (u32)(lane & 15);
    const u32 csel = (u32)((lane >> 4) << 3);
    __half* St = (__half*)(smem + SM_ST);

    for (int nt = 0; nt < 3; nt++) {
        float acc[2][4][4];
        #pragma unroll
        for (int mf = 0; mf < 2; mf++)
            #pragma unroll
            for (int nf = 0; nf < 4; nf++)
                #pragma unroll
                for (int r = 0; r < 4; r++) acc[mf][nf][r] = 0.f;

        #pragma unroll
        for (int ks = 0; ks < 8; ks++) {
            const int k0 = ks * 16;
            u32 a[2][4], bfr[4][2];
            #pragma unroll
            for (int mf = 0; mf < 2; mf++)
                ldsm4(a[mf], sb + SM_A + ((m0 + mf * 16 + arow) * 136 + csel + k0) * 2);
            #pragma unroll
            for (int h2 = 0; h2 < 2; h2++) {
                u32 r[4];
                ldsm4t(r, sb + SM_B + ((k0 + arow) * 136 + n0 + h2 * 16 + csel) * 2);
                bfr[h2*2][0] = r[0];   bfr[h2*2][1] = r[1];
                bfr[h2*2+1][0] = r[2]; bfr[h2*2+1][1] = r[3];
            }
            #pragma unroll
            for (int mf = 0; mf < 2; mf++)
                #pragma unroll
                for (int nf = 0; nf < 4; nf++)
                    mma16816(acc[mf][nf], a[mf], bfr[nf]);
        }

        // stage accum (+bias) to St as fp16 pairs
        {
            const int r0 = m0 + (lane >> 2);
            const int cb = nt * 128 + n0 + (lane & 3) * 2;
            #pragma unroll
            for (int mf = 0; mf < 2; mf++)
                #pragma unroll
                for (int nf = 0; nf < 4; nf++) {
                    int row = r0 + mf * 16, col = cb + nf * 8;
                    float b0 = sbias[col], b1 = sbias[col + 1];
                    *(u32*)&St[row * STP + col] =
                        cvt_h2(acc[mf][nf][0] + b0, acc[mf][nf][1] + b1);
                    *(u32*)&St[(row + 8) * STP + col] =
                        cvt_h2(acc[mf][nf][2] + b0, acc[mf][nf][3] + b1);
                }
        }

        if (nt < 2) {
            __syncthreads();    // all warps done reading current B tile
            const int gc = (nt + 1) * 128;
            #pragma unroll
            for (int t = 0; t < 16; t++) {
                int f = tid + 256 * t;
                int row = f >> 5, c4 = (f & 31) * 4;
                float4 v = *(const float4*)&Wqkv[row * NQKV + gc + c4];
                *(uint2*)(smem + SM_B + (row * 136 + c4) * 2) = cvt_h4(v);
            }
            __syncthreads();
        }
    }
    __syncthreads();

    // Attention: 4 threads per position (pos = tid>>2, h1 = tid&3).
    {
        const int pos = tid >> 2, h1 = tid & 3;
        const __half* rp = St + pos * STP;   // [h*96 + {q:0..31, k:32..63, v:64..95}]

        float s[4] = {0.f, 0.f, 0.f, 0.f};
        #pragma unroll
        for (int d4 = 0; d4 < 8; d4++) {
            float q4[4];
            ld_h4f(rp + h1 * 96 + d4 * 4, q4);
            #pragma unroll
            for (int h2 = 0; h2 < 4; h2++) {
                float k4[4];
                ld_h4f(rp + h2 * 96 + 32 + d4 * 4, k4);
                #pragma unroll
                for (int e = 0; e < 4; e++) s[h2] = fmaf(q4[e], k4[e], s[h2]);
            }
        }

        const float scale = 0.17677669529663687f;  // 32^-0.5
        float t0 = s[0]*scale, t1 = s[1]*scale, t2 = s[2]*scale, t3 = s[3]*scale;
        float m  = fmaxf(fmaxf(t0, t1), fmaxf(t2, t3));
        float e0 = __expf(t0 - m), e1 = __expf(t1 - m);
        float e2 = __expf(t2 - m), e3 = __expf(t3 - m);
        float inv = 1.f / (e0 + e1 + e2 + e3);
        float w0 = e0*inv, w1 = e1*inv, w2 = e2*inv, w3 = e3*inv;

        u32 hw[16];
        #pragma unroll
        for (int d4 = 0; d4 < 8; d4++) {
            float o[4] = {0.f, 0.f, 0.f, 0.f};
            float v4[4];
            ld_h4f(rp + 0*96 + 64 + d4*4, v4);
            #pragma unroll
            for (int e = 0; e < 4; e++) o[e] = fmaf(w0, v4[e], o[e]);
            ld_h4f(rp + 1*96 + 64 + d4*4, v4);
            #pragma unroll
            for (int e = 0; e < 4; e++) o[e] = fmaf(w1, v4[e], o[e]);
            ld_h4f(rp + 2*96 + 64 + d4*4, v4);
            #pragma unroll
            for (int e = 0; e < 4; e++) o[e] = fmaf(w2, v4[e], o[e]);
            ld_h4f(rp + 3*96 + 64 + d4*4, v4);
            #pragma unroll
            for (int e = 0; e < 4; e++) o[e] = fmaf(w3, v4[e], o[e]);
            hw[d4*2]     = cvt_h2(o[0], o[1]);
            hw[d4*2 + 1] = cvt_h2(o[2], o[3]);
        }

        __half* outp = g_attn_h + (size_t)(mbase + pos) * DM + h1 * 32;
        #pragma unroll
        for (int t = 0; t < 4; t++) {
            uint4 v = make_uint4(hw[4*t], hw[4*t+1], hw[4*t+2], hw[4*t+3]);
            *(uint4*)(outp + t * 8) = v;
        }
    }
}

// ---------------------------------------------------------------------------
// k2: split-K+M partials of C[b] = A2[b](128x8192) @ W_out(8192x128), fp16 mma
//   grid (NKC, 2, BATCH); each block: 64 rows x 128 cols, K=512   [R10/R12 proven]
// ---------------------------------------------------------------------------
__global__ __launch_bounds__(256, 1)
void k2_partial(const float* __restrict__ Wout)
{
    __shared__ __align__(16) __half As2[2][64 * 40];    // pitch 40
    __shared__ __align__(16) __half Bs2[2][32 * 136];   // pitch 136
    const u32 sa = smem_u32(As2);
    const u32 sbm = smem_u32(Bs2);

    const int tid = threadIdx.x;
    const int lane = tid & 31, wid = tid >> 5;
    const int kc = blockIdx.x, mb = blockIdx.y, b = blockIdx.z;
    const __half* Ab = g_attn_h + (size_t)b * DM * S_LEN + (size_t)mb * 64 * S_LEN;
    const int kb0 = kc * KCH;

    const int m0 = (wid >> 2) * 32;     // 2 warp-rows of 32
    const int n0 = (wid & 3) * 32;
    const u32 arow = (u32)(lane & 15);
    const u32 csel = (u32)((lane >> 4) << 3);

    float acc[2][4][4];
    #pragma unroll
    for (int mf = 0; mf < 2; mf++)
        #pragma unroll
        for (int nf = 0; nf < 4; nf++)
            #pragma unroll
            for (int r = 0; r < 4; r++) acc[mf][nf][r] = 0.f;

    uint4 pa;
    float4 pbf[4];
    auto gload = [&](int c) {
        const int kpos = kb0 + c * 32;
        pa = *(const uint4*)&Ab[(size_t)(tid >> 2) * S_LEN + kpos + (tid & 3) * 8];
        #pragma unroll
        for (int t = 0; t < 4; t++) {
            int f = tid + 256 * t;
            int kk = f >> 5, n4 = (f & 31) * 4;
            pbf[t] = *(const float4*)&Wout[(size_t)(kpos + kk) * DM + n4];
        }
    };
    auto sstore = [&](int buf) {
        *(uint4*)&As2[buf][(tid >> 2) * 40 + (tid & 3) * 8] = pa;
        #pragma unroll
        for (int t = 0; t < 4; t++) {
            int f = tid + 256 * t;
            int kk = f >> 5, n4 = (f & 31) * 4;
            *(uint2*)&Bs2[buf][kk * 136 + n4] = cvt_h4(pbf[t]);
        }
    };

    gload(0); sstore(0); __syncthreads();

    int buf = 0;
    for (int c = 0; c < 16; c++) {
        if (c < 15) gload(c + 1);
        #pragma unroll
        for (int kk = 0; kk < 32; kk += 16) {
            u32 a[2][4], bfr[4][2];
            #pragma unroll
            for (int h2 = 0; h2 < 2; h2++) {
                u32 r[4];
                ldsm4t(r, sbm + (u32)buf * (32*136*2) +
                          ((kk + arow) * 136 + n0 + h2 * 16 + csel) * 2);
                bfr[h2*2][0] = r[0];   bfr[h2*2][1] = r[1];
                bfr[h2*2+1][0] = r[2]; bfr[h2*2+1][1] = r[3];
            }
            #pragma unroll
            for (int mf = 0; mf < 2; mf++)
                ldsm4(a[mf], sa + (u32)buf * (64*40*2) +
                             ((m0 + mf * 16 + arow) * 40 + csel + kk) * 2);
            #pragma unroll
            for (int mf = 0; mf < 2; mf++)
                #pragma unroll
                for (int nf = 0; nf < 4; nf++)
                    mma16816(acc[mf][nf], a[mf], bfr[nf]);
        }
        if (c < 15) sstore(buf ^ 1);
        __syncthreads();
        buf ^= 1;
    }

    float* pp = g_part + (size_t)(b * NKC + kc) * DM * DM;
    const int r0 = mb * 64 + m0 + (lane >> 2);
    const int cb = n0 + (lane & 3) * 2;
    #pragma unroll
    for (int mf = 0; mf < 2; mf++)
        #pragma unroll
        for (int nf = 0; nf < 4; nf++) {
            int row = r0 + mf * 16, col = cb + nf * 8;
            *(float2*)&pp[row * DM + col] = make_float2(acc[mf][nf][0], acc[mf][nf][1]);
            *(float2*)&pp[(row + 8) * DM + col] = make_float2(acc[mf][nf][2], acc[mf][nf][3]);
        }
}

// ---------------------------------------------------------------------------
// k3: reduce partials + bias — float2/thread, 2x threads (R12 proven)
// ---------------------------------------------------------------------------
__global__ void k3_reduce(const float* __restrict__ bout, float* __restrict__ out)
{
    const int i2 = blockIdx.x * 256 + threadIdx.x;   // 0..65535 (float2 index)
    const int b  = i2 >> 13;
    const int rc2 = i2 & 8191;
    float2 s = *(const float2*)&bout[(i2 * 2) & 127];
    const float* p = g_part + (size_t)b * NKC * DM * DM + rc2 * 2;
    #pragma unroll
    for (int kc = 0; kc < NKC; kc++) {
        float2 v = *(const float2*)&p[kc * DM * DM];
        s.x += v.x; s.y += v.y;
    }
    *(float2*)&out[i2 * 2] = s;
}

// ---------------------------------------------------------------------------
extern "C" void kernel_launch(void* const* d_in, const int* in_sizes, int n_in,
                              void* d_out, int out_size)
{
    const float* x    = (const float*)d_in[0];
    const float* Wqkv = (const float*)d_in[1];
    const float* bqkv = (const float*)d_in[2];
    const float* Wout = (const float*)d_in[3];
    const float* bout = (const float*)d_in[4];
    float* out = (float*)d_out;

    cudaFuncSetAttribute(k1_qkv_attn,
                         cudaFuncAttributeMaxDynamicSharedMemorySize, SM_TOT);

    k1_qkv_attn<<<(BATCH * S_LEN) / MT1, 256, SM_TOT>>>(x, Wqkv, bqkv);

    dim3 g2(NKC, 2, BATCH);
    k2_partial<<<g2, 256>>>(Wout);

    k3_reduce<<<(BATCH * DM * DM / 2) / 256, 256>>>(bout, out);
}

// round 15
// speedup vs baseline: 1.1783x; 1.0690x over previous
#include <cuda_runtime.h>
#include <cuda_fp16.h>

typedef unsigned int u32;

// Problem constants
#define S_LEN 8192
#define BATCH 8
#define DM    128
#define NQKV  384
#define MT1   64             // rows per k1 block
#define NKC   16             // split-K chunks (kernel 2)
#define KCH   (S_LEN/NKC)    // 512

// ---- scratch (device globals; no cudaMalloc anywhere) ----
__device__ __align__(16) __half g_attn_h[BATCH * S_LEN * DM];   // 16.7 MB attn out (fp16)
__device__ float g_part[NKC * BATCH * DM * DM];                 // 8 MB split-K partials
__device__ __align__(16) __half g_wq[DM * NQKV];                // W_qkv fp16 [k][n]

// ---- k1 smem layout (bytes) ----
#define SM_BIAS 0                         // 384 f32 = 1536
#define SM_A    1536                      // [64][136] fp16 = 17408
#define SM_B    (SM_A + 17408)            // [128][136] fp16 = 34816
#define SM_ST   (SM_B + 34816)            // [64][404] fp16 = 51712
#define SM_TOT  (SM_ST + 51712)           // 105472 B -> 2 CTA/SM
#define STP     404                       // pitch in halves: 808 B rows (8B-aligned, 8B-stride 101 -> conflict-free)

// ---------------------------------------------------------------------------
__device__ __forceinline__ u32 smem_u32(const void* p) {
    u32 a;
    asm("{ .reg .u64 t; cvta.to.shared.u64 t, %1; cvt.u32.u64 %0, t; }" : "=r"(a) : "l"(p));
    return a;
}
__device__ __forceinline__ void ldsm4(u32* r, u32 a) {
    asm volatile("ldmatrix.sync.aligned.m8n8.x4.shared.b16 {%0,%1,%2,%3}, [%4];"
        : "=r"(r[0]), "=r"(r[1]), "=r"(r[2]), "=r"(r[3]) : "r"(a));
}
__device__ __forceinline__ void ldsm4t(u32* r, u32 a) {
    asm volatile("ldmatrix.sync.aligned.m8n8.x4.trans.shared.b16 {%0,%1,%2,%3}, [%4];"
        : "=r"(r[0]), "=r"(r[1]), "=r"(r[2]), "=r"(r[3]) : "r"(a));
}
__device__ __forceinline__ void mma16816(float* d, const u32* a, const u32* b) {
    asm volatile(
        "mma.sync.aligned.m16n8k16.row.col.f32.f16.f16.f32 "
        "{%0,%1,%2,%3}, {%4,%5,%6,%7}, {%8,%9}, {%0,%1,%2,%3};"
        : "+f"(d[0]), "+f"(d[1]), "+f"(d[2]), "+f"(d[3])
        : "r"(a[0]), "r"(a[1]), "r"(a[2]), "r"(a[3]), "r"(b[0]), "r"(b[1]));
}
__device__ __forceinline__ uint2 cvt_h4(float4 v) {
    __half2 a = __floats2half2_rn(v.x, v.y);
    __half2 b = __floats2half2_rn(v.z, v.w);
    uint2 r;
    r.x = *(u32*)&a;
    r.y = *(u32*)&b;
    return r;
}
__device__ __forceinline__ u32 cvt_h2(float a, float b) {
    __half2 h = __floats2half2_rn(a, b);
    return *(u32*)&h;
}
// load 4 halves at p (8B aligned) -> 4 floats
__device__ __forceinline__ void ld_h4f(const __half* p, float* f) {
    uint2 v = *(const uint2*)p;
    float2 a = __half22float2(*(__half2*)&v.x);
    float2 b = __half22float2(*(__half2*)&v.y);
    f[0] = a.x; f[1] = a.y; f[2] = b.x; f[3] = b.y;
}

// ---------------------------------------------------------------------------
// k0a: one-time W_qkv fp32 -> fp16
// ---------------------------------------------------------------------------
__global__ void k0a_convWq(const float* __restrict__ W)
{
    int idx = blockIdx.x * 256 + threadIdx.x;
    if (idx < DM * NQKV) g_wq[idx] = __float2half_rn(W[idx]);
}

// ---------------------------------------------------------------------------
// k1: qkv = x @ W_qkv + b via fp16 mma.sync; A fragments cached in registers
//     across the 3 N-tiles; 4-thread/position attention epilogue; fp16 out
// ---------------------------------------------------------------------------
__global__ __launch_bounds__(256, 2)
void k1_qkv_attn(const float* __restrict__ x, const float* __restrict__ bqkv)
{
    extern __shared__ char smem[];
    const u32 sb  = smem_u32(smem);
    const int tid = threadIdx.x;
    const int lane = tid & 31, wid = tid >> 5;
    const int mbase = blockIdx.x * MT1;

    float* sbias = (float*)(smem + SM_BIAS);
    for (int i = tid; i < NQKV; i += 256) sbias[i] = bqkv[i];

    // A tile: 64x128 fp32 -> fp16, pitch 136
    {
        const float4* xg = (const float4*)(x + (size_t)mbase * DM);
        #pragma unroll
        for (int t = 0; t < 8; t++) {
            int f = tid + 256 * t;              // 2048 float4
            int row = f >> 5, k0 = (f & 31) * 4;
            *(uint2*)(smem + SM_A + (row * 136 + k0) * 2) = cvt_h4(xg[f]);
        }
    }
    // B tile nt=0 (pre-converted fp16, uint4 loads)
    {
        const uint4* src = (const uint4*)g_wq;   // rows of 48 uint4 (384 fp16)
        #pragma unroll
        for (int t = 0; t < 8; t++) {
            int f = tid + 256 * t;               // 2048 uint4
            int row = f >> 4, c8 = (f & 15);
            *(uint4*)(smem + SM_B + (row * 136 + c8 * 8) * 2) = src[row * 48 + c8];
        }
    }
    __syncthreads();

    const int m0 = (wid >> 2) * 32;     // 2 M-groups of 32 rows
    const int n0 = (wid & 3) * 32;      // 4 N-groups of 32 cols
    const u32 arow = (u32)(lane & 15);
    const u32 csel = (u32)((lane >> 4) << 3);
    __half* St = (__half*)(smem + SM_ST);

    u32 afr[8][2][4];                   // A fragments, cached across all 3 nt tiles

    // staging helper (constant-index unrolled at each call site via nt param)
    auto stage = [&](float acc[2][4][4], int nt) {
        const int r0 = m0 + (lane >> 2);
        const int cb = nt * 128 + n0 + (lane & 3) * 2;
        #pragma unroll
        for (int mf = 0; mf < 2; mf++)
            #pragma unroll
            for (int nf = 0; nf < 4; nf++) {
                int row = r0 + mf * 16, col = cb + nf * 8;
                float b0 = sbias[col], b1 = sbias[col + 1];
                *(u32*)&St[row * STP + col] =
                    cvt_h2(acc[mf][nf][0] + b0, acc[mf][nf][1] + b1);
                *(u32*)&St[(row + 8) * STP + col] =
                    cvt_h2(acc[mf][nf][2] + b0, acc[mf][nf][3] + b1);
            }
    };

    // ---- tile nt=0: load A fragments once + compute ----
    {
        float acc[2][4][4];
        #pragma unroll
        for (int mf = 0; mf < 2; mf++)
            #pragma unroll
            for (int nf = 0; nf < 4; nf++)
                #pragma unroll
                for (int r = 0; r < 4; r++) acc[mf][nf][r] = 0.f;

        #pragma unroll
        for (int ks = 0; ks < 8; ks++) {
            const int k0 = ks * 16;
            u32 bfr[4][2];
            #pragma unroll
            for (int mf = 0; mf < 2; mf++)
                ldsm4(afr[ks][mf], sb + SM_A + ((m0 + mf * 16 + arow) * 136 + csel + k0) * 2);
            #pragma unroll
            for (int h2 = 0; h2 < 2; h2++) {
                u32 r[4];
                ldsm4t(r, sb + SM_B + ((k0 + arow) * 136 + n0 + h2 * 16 + csel) * 2);
                bfr[h2*2][0] = r[0];   bfr[h2*2][1] = r[1];
                bfr[h2*2+1][0] = r[2]; bfr[h2*2+1][1] = r[3];
            }
            #pragma unroll
            for (int mf = 0; mf < 2; mf++)
                #pragma unroll
                for (int nf = 0; nf < 4; nf++)
                    mma16816(acc[mf][nf], afr[ks][mf], bfr[nf]);
        }
        stage(acc, 0);
    }

    // ---- tiles nt=1,2: reuse cached A fragments ----
    #pragma unroll
    for (int nt = 1; nt < 3; nt++) {
        __syncthreads();    // all warps done reading current B tile
        {
            const uint4* src = (const uint4*)g_wq;
            const int gc8 = nt * 16;
            #pragma unroll
            for (int t = 0; t < 8; t++) {
                int f = tid + 256 * t;
                int row = f >> 4, c8 = (f & 15);
                *(uint4*)(smem + SM_B + (row * 136 + c8 * 8) * 2) = src[row * 48 + gc8 + c8];
            }
        }
        __syncthreads();

        float acc[2][4][4];
        #pragma unroll
        for (int mf = 0; mf < 2; mf++)
            #pragma unroll
            for (int nf = 0; nf < 4; nf++)
                #pragma unroll
                for (int r = 0; r < 4; r++) acc[mf][nf][r] = 0.f;

        #pragma unroll
        for (int ks = 0; ks < 8; ks++) {
            const int k0 = ks * 16;
            u32 bfr[4][2];
            #pragma unroll
            for (int h2 = 0; h2 < 2; h2++) {
                u32 r[4];
                ldsm4t(r, sb + SM_B + ((k0 + arow) * 136 + n0 + h2 * 16 + csel) * 2);
                bfr[h2*2][0] = r[0];   bfr[h2*2][1] = r[1];
                bfr[h2*2+1][0] = r[2]; bfr[h2*2+1][1] = r[3];
            }
            #pragma unroll
            for (int mf = 0; mf < 2; mf++)
                #pragma unroll
                for (int nf = 0; nf < 4; nf++)
                    mma16816(acc[mf][nf], afr[ks][mf], bfr[nf]);
        }
        stage(acc, nt);
    }
    __syncthreads();

    // Attention: 4 threads per position (pos = tid>>2, h1 = tid&3).
    {
        const int pos = tid >> 2, h1 = tid & 3;
        const __half* rp = St + pos * STP;   // [h*96 + {q:0..31, k:32..63, v:64..95}]

        float s[4] = {0.f, 0.f, 0.f, 0.f};
        #pragma unroll
        for (int d4 = 0; d4 < 8; d4++) {
            float q4[4];
            ld_h4f(rp + h1 * 96 + d4 * 4, q4);
            #pragma unroll
            for (int h2 = 0; h2 < 4; h2++) {
                float k4[4];
                ld_h4f(rp + h2 * 96 + 32 + d4 * 4, k4);
                #pragma unroll
                for (int e = 0; e < 4; e++) s[h2] = fmaf(q4[e], k4[e], s[h2]);
            }
        }

        const float scale = 0.17677669529663687f;  // 32^-0.5
        float t0 = s[0]*scale, t1 = s[1]*scale, t2 = s[2]*scale, t3 = s[3]*scale;
        float m  = fmaxf(fmaxf(t0, t1), fmaxf(t2, t3));
        float e0 = __expf(t0 - m), e1 = __expf(t1 - m);
        float e2 = __expf(t2 - m), e3 = __expf(t3 - m);
        float inv = 1.f / (e0 + e1 + e2 + e3);
        float w0 = e0*inv, w1 = e1*inv, w2 = e2*inv, w3 = e3*inv;

        u32 hw[16];
        #pragma unroll
        for (int d4 = 0; d4 < 8; d4++) {
            float o[4] = {0.f, 0.f, 0.f, 0.f};
            float v4[4];
            ld_h4f(rp + 0*96 + 64 + d4*4, v4);
            #pragma unroll
            for (int e = 0; e < 4; e++) o[e] = fmaf(w0, v4[e], o[e]);
            ld_h4f(rp + 1*96 + 64 + d4*4, v4);
            #pragma unroll
            for (int e = 0; e < 4; e++) o[e] = fmaf(w1, v4[e], o[e]);
            ld_h4f(rp + 2*96 + 64 + d4*4, v4);
            #pragma unroll
            for (int e = 0; e < 4; e++) o[e] = fmaf(w2, v4[e], o[e]);
            ld_h4f(rp + 3*96 + 64 + d4*4, v4);
            #pragma unroll
            for (int e = 0; e < 4; e++) o[e] = fmaf(w3, v4[e], o[e]);
            hw[d4*2]     = cvt_h2(o[0], o[1]);
            hw[d4*2 + 1] = cvt_h2(o[2], o[3]);
        }

        __half* outp = g_attn_h + (size_t)(mbase + pos) * DM + h1 * 32;
        #pragma unroll
        for (int t = 0; t < 4; t++) {
            uint4 v = make_uint4(hw[4*t], hw[4*t+1], hw[4*t+2], hw[4*t+3]);
            *(uint4*)(outp + t * 8) = v;
        }
    }
}

// ---------------------------------------------------------------------------
// k2: split-K+M partials of C[b] = A2[b](128x8192) @ W_out(8192x128), fp16 mma
//   grid (NKC, 2, BATCH); each block: 64 rows x 128 cols, K=512   [proven]
// ---------------------------------------------------------------------------
__global__ __launch_bounds__(256, 1)
void k2_partial(const float* __restrict__ Wout)
{
    __shared__ __align__(16) __half As2[2][64 * 40];    // pitch 40
    __shared__ __align__(16) __half Bs2[2][32 * 136];   // pitch 136
    const u32 sa = smem_u32(As2);
    const u32 sbm = smem_u32(Bs2);

    const int tid = threadIdx.x;
    const int lane = tid & 31, wid = tid >> 5;
    const int kc = blockIdx.x, mb = blockIdx.y, b = blockIdx.z;
    const __half* Ab = g_attn_h + (size_t)b * DM * S_LEN + (size_t)mb * 64 * S_LEN;
    const int kb0 = kc * KCH;

    const int m0 = (wid >> 2) * 32;     // 2 warp-rows of 32
    const int n0 = (wid & 3) * 32;
    const u32 arow = (u32)(lane & 15);
    const u32 csel = (u32)((lane >> 4) << 3);

    float acc[2][4][4];
    #pragma unroll
    for (int mf = 0; mf < 2; mf++)
        #pragma unroll
        for (int nf = 0; nf < 4; nf++)
            #pragma unroll
            for (int r = 0; r < 4; r++) acc[mf][nf][r] = 0.f;

    uint4 pa;
    float4 pbf[4];
    auto gload = [&](int c) {
        const int kpos = kb0 + c * 32;
        pa = *(const uint4*)&Ab[(size_t)(tid >> 2) * S_LEN + kpos + (tid & 3) * 8];
        #pragma unroll
        for (int t = 0; t < 4; t++) {
            int f = tid + 256 * t;
            int kk = f >> 5, n4 = (f & 31) * 4;
            pbf[t] = *(const float4*)&Wout[(size_t)(kpos + kk) * DM + n4];
        }
    };
    auto sstore = [&](int buf) {
        *(uint4*)&As2[buf][(tid >> 2) * 40 + (tid & 3) * 8] = pa;
        #pragma unroll
        for (int t = 0; t < 4; t++) {
            int f = tid + 256 * t;
            int kk = f >> 5, n4 = (f & 31) * 4;
            *(uint2*)&Bs2[buf][kk * 136 + n4] = cvt_h4(pbf[t]);
        }
    };

    gload(0); sstore(0); __syncthreads();

    int buf = 0;
    for (int c = 0; c < 16; c++) {
        if (c < 15) gload(c + 1);
        #pragma unroll
        for (int kk = 0; kk < 32; kk += 16) {
            u32 a[2][4], bfr[4][2];
            #pragma unroll
            for (int h2 = 0; h2 < 2; h2++) {
                u32 r[4];
                ldsm4t(r, sbm + (u32)buf * (32*136*2) +
                          ((kk + arow) * 136 + n0 + h2 * 16 + csel) * 2);
                bfr[h2*2][0] = r[0];   bfr[h2*2][1] = r[1];
                bfr[h2*2+1][0] = r[2]; bfr[h2*2+1][1] = r[3];
            }
            #pragma unroll
            for (int mf = 0; mf < 2; mf++)
                ldsm4(a[mf], sa + (u32)buf * (64*40*2) +
                             ((m0 + mf * 16 + arow) * 40 + csel + kk) * 2);
            #pragma unroll
            for (int mf = 0; mf < 2; mf++)
                #pragma unroll
                for (int nf = 0; nf < 4; nf++)
                    mma16816(acc[mf][nf], a[mf], bfr[nf]);
        }
        if (c < 15) sstore(buf ^ 1);
        __syncthreads();
        buf ^= 1;
    }

    float* pp = g_part + (size_t)(b * NKC + kc) * DM * DM;
    const int r0 = mb * 64 + m0 + (lane >> 2);
    const int cb = n0 + (lane & 3) * 2;
    #pragma unroll
    for (int mf = 0; mf < 2; mf++)
        #pragma unroll
        for (int nf = 0; nf < 4; nf++) {
            int row = r0 + mf * 16, col = cb + nf * 8;
            *(float2*)&pp[row * DM + col] = make_float2(acc[mf][nf][0], acc[mf][nf][1]);
            *(float2*)&pp[(row + 8) * DM + col] = make_float2(acc[mf][nf][2], acc[mf][nf][3]);
        }
}

// ---------------------------------------------------------------------------
// k3: reduce partials + bias — float2/thread (R12 proven)
// ---------------------------------------------------------------------------
__global__ void k3_reduce(const float* __restrict__ bout, float* __restrict__ out)
{
    const int i2 = blockIdx.x * 256 + threadIdx.x;   // 0..65535 (float2 index)
    const int b  = i2 >> 13;
    const int rc2 = i2 & 8191;
    float2 s = *(const float2*)&bout[(i2 * 2) & 127];
    const float* p = g_part + (size_t)b * NKC * DM * DM + rc2 * 2;
    #pragma unroll
    for (int kc = 0; kc < NKC; kc++) {
        float2 v = *(const float2*)&p[kc * DM * DM];
        s.x += v.x; s.y += v.y;
    }
    *(float2*)&out[i2 * 2] = s;
}

// ---------------------------------------------------------------------------
extern "C" void kernel_launch(void* const* d_in, const int* in_sizes, int n_in,
                              void* d_out, int out_size)
{
    const float* x    = (const float*)d_in[0];
    const float* Wqkv = (const float*)d_in[1];
    const float* bqkv = (const float*)d_in[2];
    const float* Wout = (const float*)d_in[3];
    const float* bout = (const float*)d_in[4];
    float* out = (float*)d_out;

    cudaFuncSetAttribute(k1_qkv_attn,
                         cudaFuncAttributeMaxDynamicSharedMemorySize, SM_TOT);

    k0a_convWq<<<(DM * NQKV + 255) / 256, 256>>>(Wqkv);

    k1_qkv_attn<<<(BATCH * S_LEN) / MT1, 256, SM_TOT>>>(x, bqkv);

    dim3 g2(NKC, 2, BATCH);
    k2_partial<<<g2, 256>>>(Wout);

    k3_reduce<<<(BATCH * DM * DM / 2) / 256, 256>>>(bout, out);
}